// round 1
// baseline (speedup 1.0000x reference)
#include <cuda_runtime.h>
#include <math.h>

#define NN 8192
#define FF 8
#define THRESH 0.9f

typedef unsigned long long ull;

// Scratch (device globals; no allocation allowed)
__device__ float g_xn[NN * FF];    // normalized features, row-major
__device__ float g_xT[FF * NN];    // raw features, transposed [f][j]
__device__ float g_corr[NN * FF];  // sparse fidelity-hit corrections

// ---------- packed f32x2 helpers (Blackwell FFMA2) ----------
__device__ __forceinline__ ull pk2(float x, float y) {
    ull r; asm("mov.b64 %0, {%1, %2};" : "=l"(r) : "f"(x), "f"(y)); return r;
}
__device__ __forceinline__ void fma2(ull& d, ull a, ull b) {
    asm("fma.rn.f32x2 %0, %1, %2, %0;" : "+l"(d) : "l"(a), "l"(b));
}
__device__ __forceinline__ float hsum2(ull v) {
    float a, b; asm("mov.b64 {%0, %1}, %2;" : "=f"(a), "=f"(b) : "l"(v)); return a + b;
}

// ---------- kernel 1: normalize, transpose, zero corrections ----------
__global__ void k_prep(const float* __restrict__ x) {
    int i = blockIdx.x * blockDim.x + threadIdx.x;
    if (i >= NN) return;
    float4 a = *(const float4*)(x + i * FF);
    float4 b = *(const float4*)(x + i * FF + 4);
    float s = a.x*a.x + a.y*a.y + a.z*a.z + a.w*a.w
            + b.x*b.x + b.y*b.y + b.z*b.z + b.w*b.w;
    float inv = 1.0f / (sqrtf(s) + 1e-12f);
    float xf[8] = {a.x, a.y, a.z, a.w, b.x, b.y, b.z, b.w};
#pragma unroll
    for (int f = 0; f < FF; ++f) {
        g_xn[i * FF + f] = xf[f] * inv;
        g_xT[f * NN + i] = xf[f];
        g_corr[i * FF + f] = 0.0f;
    }
}

// ---------- kernel 2: fidelity hits (symmetric half) + corrections ----------
// Tile grid 128x128 of 64x64 tiles; ti>tj blocks exit immediately.
__global__ void __launch_bounds__(256) k_fid(const float* __restrict__ adj,
                                             const float* __restrict__ x) {
    int ti = blockIdx.y, tj = blockIdx.x;
    if (ti > tj) return;
    __shared__ float sI[64 * 9];   // stride 9 -> conflict-free scalar LDS
    __shared__ float sJ[64 * 9];
    int t = threadIdx.x;
    for (int k = t; k < 64 * FF; k += 256) {
        int r = k >> 3, f = k & 7;
        sI[r * 9 + f] = g_xn[(ti * 64 + r) * FF + f];
        sJ[r * 9 + f] = g_xn[(tj * 64 + r) * FF + f];
    }
    __syncthreads();

    int is = (t & 15) << 2;   // 4 i-rows per thread
    int js = (t >> 4) << 2;   // 4 j-rows per thread

    float xi[4][8], xj[4][8];
#pragma unroll
    for (int a = 0; a < 4; ++a)
#pragma unroll
        for (int f = 0; f < FF; ++f) {
            xi[a][f] = sI[(is + a) * 9 + f];
            xj[a][f] = sJ[(js + a) * 9 + f];
        }

#pragma unroll
    for (int a = 0; a < 4; ++a) {
#pragma unroll
        for (int b = 0; b < 4; ++b) {
            float d = 0.0f;
#pragma unroll
            for (int f = 0; f < FF; ++f) d = fmaf(xi[a][f], xj[b][f], d);
            if (d * d >= THRESH) {             // rare (~1e-4 of pairs)
                int i = ti * 64 + is + a;
                int j = tj * 64 + js + b;
                if (i < j) {
                    float aij = __ldg(adj + (size_t)i * NN + j);
                    float aji = __ldg(adj + (size_t)j * NN + i);
                    float wi = 1.0f - aij;     // max(adj,1)-adj
                    float wj = 1.0f - aji;
#pragma unroll
                    for (int f = 0; f < FF; ++f) {
                        atomicAdd(&g_corr[i * FF + f], wi * __ldg(x + j * FF + f));
                        atomicAdd(&g_corr[j * FF + f], wj * __ldg(x + i * FF + f));
                    }
                }
            }
        }
    }
}

// ---------- kernel 3: stream adjacency, accumulate, fused MLP ----------
#define CH 1024
#define TPB_ADJ 128

// smem weight offsets
#define OW0 0
#define OB0 128
#define OW1 144
#define OB1 400
#define OW2 416
#define OB2 608
#define OW3 620
#define OB3 716
#define OW4 724
#define OB4 756
#define OW5 760
#define OB5 776
#define OW6 780
#define OB6 784

__global__ void __launch_bounds__(TPB_ADJ) k_adj(
    const float* __restrict__ adj,
    const float* __restrict__ Wfm, const float* __restrict__ bfm,
    const float* __restrict__ Wc1, const float* __restrict__ bc1,
    const float* __restrict__ Wp1, const float* __restrict__ bp1,
    const float* __restrict__ Wc2, const float* __restrict__ bc2,
    const float* __restrict__ Wp2, const float* __restrict__ bp2,
    const float* __restrict__ Wc3, const float* __restrict__ bc3,
    const float* __restrict__ Wh,  const float* __restrict__ bh,
    float* __restrict__ out)
{
    __shared__ float sx[FF][CH];   // x transposed chunk [f][j]
    __shared__ float swt[792];     // all MLP weights

    int tid = threadIdx.x, warp = tid >> 5, lane = tid & 31;

    // stage MLP weights once
    {
        const float* srcs[14] = {Wfm, bfm, Wc1, bc1, Wp1, bp1, Wc2, bc2,
                                 Wp2, bp2, Wc3, bc3, Wh, bh};
        const int szs[14] = {128, 16, 256, 16, 192, 12, 96, 8, 32, 4, 16, 4, 4, 1};
        int off = 0;
        for (int a = 0; a < 14; ++a) {
            for (int k = tid; k < szs[a]; k += TPB_ADJ) swt[off + k] = srcs[a][k];
            off += szs[a];
        }
    }

    int rowbase = blockIdx.x * 16 + warp * 4;  // 4 rows per warp
    const float* a0p = adj + (size_t)rowbase * NN;
    const float* a1p = a0p + NN;
    const float* a2p = a1p + NN;
    const float* a3p = a2p + NN;

    ull acc[4][FF];   // f32x2: components = (even-j, odd-j) partial sums
#pragma unroll
    for (int r = 0; r < 4; ++r)
#pragma unroll
        for (int f = 0; f < FF; ++f) acc[r][f] = 0ULL;

    for (int c = 0; c < NN; c += CH) {
        __syncthreads();
        // cooperative load of x chunk (transposed), coalesced float4
        for (int idx = tid; idx < FF * CH / 4; idx += TPB_ADJ) {
            int f = idx >> 8;               // CH/4 == 256
            int j4 = (idx & 255) << 2;
            *(float4*)&sx[f][j4] = *(const float4*)&g_xT[f * NN + c + j4];
        }
        __syncthreads();

#pragma unroll 2
        for (int s0 = 0; s0 < CH; s0 += 128) {
            int jl = s0 + lane * 4;
            int j = c + jl;
            float4 A0 = __ldg((const float4*)(a0p + j));
            float4 A1 = __ldg((const float4*)(a1p + j));
            float4 A2 = __ldg((const float4*)(a2p + j));
            float4 A3 = __ldg((const float4*)(a3p + j));
            ull ae[4], ao[4];
            ae[0] = pk2(A0.x, A0.y); ao[0] = pk2(A0.z, A0.w);
            ae[1] = pk2(A1.x, A1.y); ao[1] = pk2(A1.z, A1.w);
            ae[2] = pk2(A2.x, A2.y); ao[2] = pk2(A2.z, A2.w);
            ae[3] = pk2(A3.x, A3.y); ao[3] = pk2(A3.z, A3.w);
#pragma unroll
            for (int f = 0; f < FF; ++f) {
                float4 X = *(const float4*)&sx[f][jl];
                ull xe = pk2(X.x, X.y), xo = pk2(X.z, X.w);
                fma2(acc[0][f], ae[0], xe); fma2(acc[0][f], ao[0], xo);
                fma2(acc[1][f], ae[1], xe); fma2(acc[1][f], ao[1], xo);
                fma2(acc[2][f], ae[2], xe); fma2(acc[2][f], ao[2], xo);
                fma2(acc[3][f], ae[3], xe); fma2(acc[3][f], ao[3], xo);
            }
        }
    }

    // combine packed halves, butterfly-reduce across the 32 j-lanes
    float v[32];
#pragma unroll
    for (int r = 0; r < 4; ++r)
#pragma unroll
        for (int f = 0; f < FF; ++f) v[r * 8 + f] = hsum2(acc[r][f]);
#pragma unroll
    for (int o = 16; o; o >>= 1)
#pragma unroll
        for (int k = 0; k < 32; ++k) v[k] += __shfl_xor_sync(0xffffffffu, v[k], o);

    if (lane < 4) {
        int row = rowbase + lane;
        float s[8];
#pragma unroll
        for (int f = 0; f < FF; ++f) s[f] = v[lane * 8 + f] + g_corr[row * FF + f];

        float h0[16];
#pragma unroll
        for (int o = 0; o < 16; ++o) {
            float t = swt[OB0 + o];
#pragma unroll
            for (int i = 0; i < 8; ++i) t = fmaf(s[i], swt[OW0 + i * 16 + o], t);
            h0[o] = tanhf(t);
        }
        float h1[16];
#pragma unroll
        for (int o = 0; o < 16; ++o) {
            float t = swt[OB1 + o];
#pragma unroll
            for (int i = 0; i < 16; ++i) t = fmaf(h0[i], swt[OW1 + i * 16 + o], t);
            h1[o] = tanhf(t);
        }
        float h2[12];
#pragma unroll
        for (int o = 0; o < 12; ++o) {
            float t = swt[OB2 + o];
#pragma unroll
            for (int i = 0; i < 16; ++i) t = fmaf(h1[i], swt[OW2 + i * 12 + o], t);
            h2[o] = tanhf(t);
        }
        float h3[8];
#pragma unroll
        for (int o = 0; o < 8; ++o) {
            float t = swt[OB3 + o];
#pragma unroll
            for (int i = 0; i < 12; ++i) t = fmaf(h2[i], swt[OW3 + i * 8 + o], t);
            h3[o] = tanhf(t);
        }
        float h4[4];
#pragma unroll
        for (int o = 0; o < 4; ++o) {
            float t = swt[OB4 + o];
#pragma unroll
            for (int i = 0; i < 8; ++i) t = fmaf(h3[i], swt[OW4 + i * 4 + o], t);
            h4[o] = tanhf(t);
        }
        float h5[4];
#pragma unroll
        for (int o = 0; o < 4; ++o) {
            float t = swt[OB5 + o];
#pragma unroll
            for (int i = 0; i < 4; ++i) t = fmaf(h4[i], swt[OW5 + i * 4 + o], t);
            h5[o] = tanhf(t);
        }
        float z = swt[OB6];
#pragma unroll
        for (int i = 0; i < 4; ++i) z = fmaf(h5[i], swt[OW6 + i], z);
        out[row] = 1.0f / (1.0f + expf(-z));
    }
}

extern "C" void kernel_launch(void* const* d_in, const int* in_sizes, int n_in,
                              void* d_out, int out_size) {
    const float* adj = (const float*)d_in[0];
    const float* x   = (const float*)d_in[1];
    const float* Wfm = (const float*)d_in[2];
    const float* bfm = (const float*)d_in[3];
    const float* Wc1 = (const float*)d_in[4];
    const float* bc1 = (const float*)d_in[5];
    const float* Wp1 = (const float*)d_in[6];
    const float* bp1 = (const float*)d_in[7];
    const float* Wc2 = (const float*)d_in[8];
    const float* bc2 = (const float*)d_in[9];
    const float* Wp2 = (const float*)d_in[10];
    const float* bp2 = (const float*)d_in[11];
    const float* Wc3 = (const float*)d_in[12];
    const float* bc3 = (const float*)d_in[13];
    const float* Wh  = (const float*)d_in[14];
    const float* bh  = (const float*)d_in[15];
    float* out = (float*)d_out;

    k_prep<<<NN / 256, 256>>>(x);
    k_fid<<<dim3(128, 128), 256>>>(adj, x);
    k_adj<<<NN / 16, TPB_ADJ>>>(adj, Wfm, bfm, Wc1, bc1, Wp1, bp1,
                                Wc2, bc2, Wp2, bp2, Wc3, bc3, Wh, bh, out);
}

// round 3
// speedup vs baseline: 1.0862x; 1.0862x over previous
#include <cuda_runtime.h>
#include <math.h>

#define NN 8192
#define FF 8
#define THRESH 0.9f
#define CH 1024
#define TPB 128

typedef unsigned long long ull;

// Scratch (device globals; no allocation allowed)
__device__ float g_xn [NN * FF];   // normalized features, row-major
__device__ float g_xnT[FF * NN];   // normalized features, transposed [f][j]
__device__ float g_xT [FF * NN];   // raw features, transposed [f][j]

// ---------- packed f32x2 helpers ----------
__device__ __forceinline__ ull pk2(float x, float y) {
    ull r; asm("mov.b64 %0, {%1, %2};" : "=l"(r) : "f"(x), "f"(y)); return r;
}
__device__ __forceinline__ void up2(float& x, float& y, ull v) {
    asm("mov.b64 {%0, %1}, %2;" : "=f"(x), "=f"(y) : "l"(v));
}
__device__ __forceinline__ void fma2(ull& d, ull a, ull b) {
    asm("fma.rn.f32x2 %0, %1, %2, %0;" : "+l"(d) : "l"(a), "l"(b));
}
__device__ __forceinline__ float hsum2(ull v) {
    float a, b; up2(a, b, v); return a + b;
}

// ---------- kernel 1: normalize + transposes ----------
__global__ void k_prep(const float* __restrict__ x) {
    int i = blockIdx.x * blockDim.x + threadIdx.x;
    if (i >= NN) return;
    float4 a = *(const float4*)(x + i * FF);
    float4 b = *(const float4*)(x + i * FF + 4);
    float s = a.x*a.x + a.y*a.y + a.z*a.z + a.w*a.w
            + b.x*b.x + b.y*b.y + b.z*b.z + b.w*b.w;
    float inv = 1.0f / (sqrtf(s) + 1e-12f);
    float xf[8] = {a.x, a.y, a.z, a.w, b.x, b.y, b.z, b.w};
#pragma unroll
    for (int f = 0; f < FF; ++f) {
        float xn = xf[f] * inv;
        g_xn [i * FF + f] = xn;
        g_xnT[f * NN + i] = xn;
        g_xT [f * NN + i] = xf[f];
    }
}

// ---------- fused kernel: stream adj, inline fid, accumulate, MLP ----------
// smem weight offsets
#define OW0 0
#define OB0 128
#define OW1 144
#define OB1 400
#define OW2 416
#define OB2 608
#define OW3 620
#define OB3 716
#define OW4 724
#define OB4 756
#define OW5 760
#define OB5 776
#define OW6 780
#define OB6 784

__global__ void __launch_bounds__(TPB, 3) k_main(
    const float* __restrict__ adj, const float* __restrict__ x,
    const float* __restrict__ Wfm, const float* __restrict__ bfm,
    const float* __restrict__ Wc1, const float* __restrict__ bc1,
    const float* __restrict__ Wp1, const float* __restrict__ bp1,
    const float* __restrict__ Wc2, const float* __restrict__ bc2,
    const float* __restrict__ Wp2, const float* __restrict__ bp2,
    const float* __restrict__ Wc3, const float* __restrict__ bc3,
    const float* __restrict__ Wh,  const float* __restrict__ bh,
    float* __restrict__ out)
{
    __shared__ float sxn[FF][CH];  // normalized chunk [f][j]
    __shared__ float sxr[FF][CH];  // raw chunk        [f][j]
    __shared__ float swt[792];

    int tid = threadIdx.x, warp = tid >> 5, lane = tid & 31;

    // stage MLP weights once
    {
        const float* srcs[14] = {Wfm, bfm, Wc1, bc1, Wp1, bp1, Wc2, bc2,
                                 Wp2, bp2, Wc3, bc3, Wh, bh};
        const int szs[14] = {128, 16, 256, 16, 192, 12, 96, 8, 32, 4, 16, 4, 4, 1};
        int off = 0;
        for (int a = 0; a < 14; ++a) {
            for (int k = tid; k < szs[a]; k += TPB) swt[off + k] = srcs[a][k];
            off += szs[a];
        }
    }

    int rowbase = blockIdx.x * 16 + warp * 4;   // 4 rows per warp
    const float* ap[4];
#pragma unroll
    for (int r = 0; r < 4; ++r) ap[r] = adj + (size_t)(rowbase + r) * NN;

    // normalized features of my 4 rows (scalar; duplicated on the fly)
    float xni[4][FF];
#pragma unroll
    for (int r = 0; r < 4; ++r)
#pragma unroll
        for (int f = 0; f < FF; ++f) xni[r][f] = g_xn[(rowbase + r) * FF + f];

    ull acc[4][FF];   // f32x2: (even-j, odd-j) partial sums
#pragma unroll
    for (int r = 0; r < 4; ++r)
#pragma unroll
        for (int f = 0; f < FF; ++f) acc[r][f] = 0ULL;

    for (int c = 0; c < NN; c += CH) {
        __syncthreads();
        for (int idx = tid; idx < FF * CH / 4; idx += TPB) {
            int f = idx >> 8;               // CH/4 == 256
            int j4 = (idx & 255) << 2;
            *(float4*)&sxn[f][j4] = *(const float4*)&g_xnT[f * NN + c + j4];
            *(float4*)&sxr[f][j4] = *(const float4*)&g_xT [f * NN + c + j4];
        }
        __syncthreads();

        for (int s0 = 0; s0 < CH; s0 += 128) {
            int jl = s0 + lane * 4;
            int j = c + jl;
            // adjacency: 4 rows x 4 j
            float4 A[4];
#pragma unroll
            for (int r = 0; r < 4; ++r) A[r] = __ldg((const float4*)(ap[r] + j));

            // dots: d2[r][p] = packed (d_j0,d_j1) / (d_j2,d_j3)
            ull d2[4][2];
#pragma unroll
            for (int r = 0; r < 4; ++r) { d2[r][0] = 0ULL; d2[r][1] = 0ULL; }
#pragma unroll
            for (int f = 0; f < FF; ++f) {
                float4 Xn = *(const float4*)&sxn[f][jl];
                ull xn0 = pk2(Xn.x, Xn.y), xn1 = pk2(Xn.z, Xn.w);
#pragma unroll
                for (int r = 0; r < 4; ++r) {
                    ull xi = pk2(xni[r][f], xni[r][f]);
                    fma2(d2[r][0], xn0, xi);
                    fma2(d2[r][1], xn1, xi);
                }
            }
            // coefficients: c = (d*d >= T) ? 1 : a   (diag fixed post-loop)
            ull c2[4][2];
#pragma unroll
            for (int r = 0; r < 4; ++r) {
                float d0, d1, d2s, d3;
                up2(d0, d1, d2[r][0]);
                up2(d2s, d3, d2[r][1]);
                float c0 = (d0 * d0  >= THRESH) ? 1.0f : A[r].x;
                float c1 = (d1 * d1  >= THRESH) ? 1.0f : A[r].y;
                float c2s= (d2s* d2s >= THRESH) ? 1.0f : A[r].z;
                float c3 = (d3 * d3  >= THRESH) ? 1.0f : A[r].w;
                c2[r][0] = pk2(c0, c1);
                c2[r][1] = pk2(c2s, c3);
            }
            // accumulate: acc[r][f] += c * x_j[f]
#pragma unroll
            for (int f = 0; f < FF; ++f) {
                float4 Xr = *(const float4*)&sxr[f][jl];
                ull xr0 = pk2(Xr.x, Xr.y), xr1 = pk2(Xr.z, Xr.w);
#pragma unroll
                for (int r = 0; r < 4; ++r) {
                    fma2(acc[r][f], c2[r][0], xr0);
                    fma2(acc[r][f], c2[r][1], xr1);
                }
            }
        }
    }

    // combine packed halves, butterfly-reduce across the 32 j-lanes
    float v[32];
#pragma unroll
    for (int r = 0; r < 4; ++r)
#pragma unroll
        for (int f = 0; f < FF; ++f) v[r * 8 + f] = hsum2(acc[r][f]);
#pragma unroll
    for (int o = 16; o; o >>= 1)
#pragma unroll
        for (int k = 0; k < 32; ++k) v[k] += __shfl_xor_sync(0xffffffffu, v[k], o);

    if (lane < 4) {
        int row = rowbase + lane;
        // diagonal always hit (d=1): replace the wrongly-added 1*x_i by a_ii*x_i
        float aii = __ldg(adj + (size_t)row * NN + row);
        float w = aii - 1.0f;
        float s[8];
#pragma unroll
        for (int f = 0; f < FF; ++f)
            s[f] = v[lane * 8 + f] + w * __ldg(x + row * FF + f);

        float h0[16];
#pragma unroll
        for (int o = 0; o < 16; ++o) {
            float t = swt[OB0 + o];
#pragma unroll
            for (int i = 0; i < 8; ++i) t = fmaf(s[i], swt[OW0 + i * 16 + o], t);
            h0[o] = tanhf(t);
        }
        float h1[16];
#pragma unroll
        for (int o = 0; o < 16; ++o) {
            float t = swt[OB1 + o];
#pragma unroll
            for (int i = 0; i < 16; ++i) t = fmaf(h0[i], swt[OW1 + i * 16 + o], t);
            h1[o] = tanhf(t);
        }
        float h2[12];
#pragma unroll
        for (int o = 0; o < 12; ++o) {
            float t = swt[OB2 + o];
#pragma unroll
            for (int i = 0; i < 16; ++i) t = fmaf(h1[i], swt[OW2 + i * 12 + o], t);
            h2[o] = tanhf(t);
        }
        float h3[8];
#pragma unroll
        for (int o = 0; o < 8; ++o) {
            float t = swt[OB3 + o];
#pragma unroll
            for (int i = 0; i < 12; ++i) t = fmaf(h2[i], swt[OW3 + i * 8 + o], t);
            h3[o] = tanhf(t);
        }
        float h4[4];
#pragma unroll
        for (int o = 0; o < 4; ++o) {
            float t = swt[OB4 + o];
#pragma unroll
            for (int i = 0; i < 8; ++i) t = fmaf(h3[i], swt[OW4 + i * 4 + o], t);
            h4[o] = tanhf(t);
        }
        float h5[4];
#pragma unroll
        for (int o = 0; o < 4; ++o) {
            float t = swt[OB5 + o];
#pragma unroll
            for (int i = 0; i < 4; ++i) t = fmaf(h4[i], swt[OW5 + i * 4 + o], t);
            h5[o] = tanhf(t);
        }
        float z = swt[OB6];
#pragma unroll
        for (int i = 0; i < 4; ++i) z = fmaf(h5[i], swt[OW6 + i], z);
        out[row] = 1.0f / (1.0f + expf(-z));
    }
}

extern "C" void kernel_launch(void* const* d_in, const int* in_sizes, int n_in,
                              void* d_out, int out_size) {
    const float* adj = (const float*)d_in[0];
    const float* x   = (const float*)d_in[1];
    const float* Wfm = (const float*)d_in[2];
    const float* bfm = (const float*)d_in[3];
    const float* Wc1 = (const float*)d_in[4];
    const float* bc1 = (const float*)d_in[5];
    const float* Wp1 = (const float*)d_in[6];
    const float* bp1 = (const float*)d_in[7];
    const float* Wc2 = (const float*)d_in[8];
    const float* bc2 = (const float*)d_in[9];
    const float* Wp2 = (const float*)d_in[10];
    const float* bp2 = (const float*)d_in[11];
    const float* Wc3 = (const float*)d_in[12];
    const float* bc3 = (const float*)d_in[13];
    const float* Wh  = (const float*)d_in[14];
    const float* bh  = (const float*)d_in[15];
    float* out = (float*)d_out;

    k_prep<<<NN / TPB, TPB>>>(x);
    k_main<<<NN / 16, TPB>>>(adj, x, Wfm, bfm, Wc1, bc1, Wp1, bp1,
                             Wc2, bc2, Wp2, bp2, Wc3, bc3, Wh, bh, out);
}

// round 4
// speedup vs baseline: 1.8021x; 1.6591x over previous
#include <cuda_runtime.h>
#include <math.h>

#define NN 8192
#define FF 8
#define THRESH 0.9f
#define CH 1024
#define ATPB 128
#define FTPB 256
#define TILE 128
#define NT (NN / TILE)              // 64 tile-rows
#define NFIDB (NT * (NT + 1) / 2)   // 2080 upper-triangle tiles

typedef unsigned long long ull;

__device__ float g_corr[NN * FF];   // sparse fidelity corrections

// ---------- packed f32x2 helpers ----------
__device__ __forceinline__ ull pk2(float x, float y) {
    ull r; asm("mov.b64 %0, {%1, %2};" : "=l"(r) : "f"(x), "f"(y)); return r;
}
__device__ __forceinline__ void up2(float& x, float& y, ull v) {
    asm("mov.b64 {%0, %1}, %2;" : "=f"(x), "=f"(y) : "l"(v));
}
__device__ __forceinline__ void fma2(ull& d, ull a, ull b) {
    asm("fma.rn.f32x2 %0, %1, %2, %0;" : "+l"(d) : "l"(a), "l"(b));
}
__device__ __forceinline__ float hsum2(ull v) {
    float a, b; up2(a, b, v); return a + b;
}

// ---------- kernel 1: fidelity hits over upper-triangle 128x128 tiles ----------
__global__ void __launch_bounds__(FTPB) k_fid(const float* __restrict__ adj,
                                              const float* __restrict__ x) {
    __shared__ ull  sIp[TILE * FF];      // xn_i packed (v,v), [i][f]  (8 KB)
    __shared__ float sJ[FF][TILE];       // xn_j, [f][j]               (4 KB)

    // decode linear block id -> (ti, tj), ti <= tj
    int b = blockIdx.x;
    int ti = (int)(((2 * NT + 1) - sqrtf((float)((2 * NT + 1) * (2 * NT + 1)) - 8.0f * (float)b)) * 0.5f);
    if (ti < 0) ti = 0;
    if (ti > NT - 1) ti = NT - 1;
#define RS(r) ((r) * NT - ((r) * ((r) - 1)) / 2)
    while (ti > 0 && RS(ti) > b) --ti;
    while (RS(ti + 1) <= b) ++ti;
    int tj = ti + (b - RS(ti));
#undef RS

    int t = threadIdx.x;
    // stage: first 128 threads handle I-tile rows, next 128 handle J-tile rows
    {
        int r = t & 127;
        int row = ((t < 128) ? ti : tj) * TILE + r;
        float4 a = *(const float4*)(x + row * FF);
        float4 c = *(const float4*)(x + row * FF + 4);
        float s = a.x*a.x + a.y*a.y + a.z*a.z + a.w*a.w
                + c.x*c.x + c.y*c.y + c.z*c.z + c.w*c.w;
        float inv = 1.0f / (sqrtf(s) + 1e-12f);
        float v[8] = {a.x, a.y, a.z, a.w, c.x, c.y, c.z, c.w};
        if (t < 128) {
#pragma unroll
            for (int f = 0; f < FF; ++f) { float xn = v[f] * inv; sIp[r * FF + f] = pk2(xn, xn); }
        } else {
#pragma unroll
            for (int f = 0; f < FF; ++f) sJ[f][r] = v[f] * inv;
        }
    }
    __syncthreads();

    int w = t >> 5, lane = t & 31;
    int j0 = lane * 4;
    // register-cache xj packed pairs
    ull xj0[FF], xj1[FF];
#pragma unroll
    for (int f = 0; f < FF; ++f) {
        float4 v = *(const float4*)&sJ[f][j0];
        xj0[f] = pk2(v.x, v.y);
        xj1[f] = pk2(v.z, v.w);
    }
    int gjb = tj * TILE + j0;

#pragma unroll 4
    for (int ii = 0; ii < 16; ++ii) {
        int i = w * 16 + ii;
        ull d0 = 0ULL, d1 = 0ULL;
#pragma unroll
        for (int f = 0; f < FF; ++f) {
            ull xi = sIp[i * FF + f];      // LDS.64 broadcast
            fma2(d0, xi, xj0[f]);
            fma2(d1, xi, xj1[f]);
        }
        float da, db, dc, dd;
        up2(da, db, d0); up2(dc, dd, d1);
        int gi = ti * TILE + i;
        bool h0 = (da * da >= THRESH) && (gi < gjb + 0);
        bool h1 = (db * db >= THRESH) && (gi < gjb + 1);
        bool h2 = (dc * dc >= THRESH) && (gi < gjb + 2);
        bool h3 = (dd * dd >= THRESH) && (gi < gjb + 3);
        if (h0 | h1 | h2 | h3) {           // rare
            float4 xia = *(const float4*)(x + gi * FF);
            float4 xib = *(const float4*)(x + gi * FF + 4);
            float xi8[8] = {xia.x, xia.y, xia.z, xia.w, xib.x, xib.y, xib.z, xib.w};
            bool hh[4] = {h0, h1, h2, h3};
#pragma unroll
            for (int k = 0; k < 4; ++k) {
                if (hh[k]) {
                    int gj = gjb + k;
                    float aij = __ldg(adj + (size_t)gi * NN + gj);
                    float aji = __ldg(adj + (size_t)gj * NN + gi);
                    float wi = 1.0f - aij, wj = 1.0f - aji;
#pragma unroll
                    for (int f = 0; f < FF; ++f) {
                        atomicAdd(&g_corr[gi * FF + f], wi * __ldg(x + gj * FF + f));
                        atomicAdd(&g_corr[gj * FF + f], wj * xi8[f]);
                    }
                }
            }
        }
    }
}

// ---------- kernel 2: stream adjacency, accumulate, fused MLP ----------
// smem weight offsets
#define OW0 0
#define OB0 128
#define OW1 144
#define OB1 400
#define OW2 416
#define OB2 608
#define OW3 620
#define OB3 716
#define OW4 724
#define OB4 756
#define OW5 760
#define OB5 776
#define OW6 780
#define OB6 784

__global__ void __launch_bounds__(ATPB, 4) k_adj(
    const float* __restrict__ adj, const float* __restrict__ x,
    const float* __restrict__ Wfm, const float* __restrict__ bfm,
    const float* __restrict__ Wc1, const float* __restrict__ bc1,
    const float* __restrict__ Wp1, const float* __restrict__ bp1,
    const float* __restrict__ Wc2, const float* __restrict__ bc2,
    const float* __restrict__ Wp2, const float* __restrict__ bp2,
    const float* __restrict__ Wc3, const float* __restrict__ bc3,
    const float* __restrict__ Wh,  const float* __restrict__ bh,
    float* __restrict__ out)
{
    __shared__ float sxr[FF][CH];   // x chunk, transposed on the fly (32 KB)
    __shared__ float swt[792];

    int tid = threadIdx.x, warp = tid >> 5, lane = tid & 31;

    {   // stage MLP weights once
        const float* srcs[14] = {Wfm, bfm, Wc1, bc1, Wp1, bp1, Wc2, bc2,
                                 Wp2, bp2, Wc3, bc3, Wh, bh};
        const int szs[14] = {128, 16, 256, 16, 192, 12, 96, 8, 32, 4, 16, 4, 4, 1};
        int off = 0;
        for (int a = 0; a < 14; ++a) {
            for (int k = tid; k < szs[a]; k += ATPB) swt[off + k] = srcs[a][k];
            off += szs[a];
        }
    }

    int rowbase = blockIdx.x * 16 + warp * 4;
    const float* abase = adj + (size_t)rowbase * NN + lane * 4;

    ull acc[4][FF];
#pragma unroll
    for (int r = 0; r < 4; ++r)
#pragma unroll
        for (int f = 0; f < FF; ++f) acc[r][f] = 0ULL;

    for (int c = 0; c < NN; c += CH) {
        __syncthreads();
        // stage x chunk transposed: coalesced float4 reads, scalar smem writes
        const float4* xs = (const float4*)x + c * 2;
        for (int idx = tid; idx < CH * 2; idx += ATPB) {
            float4 v = __ldg(xs + idx);
            int j = idx >> 1, fb = (idx & 1) << 2;
            sxr[fb + 0][j] = v.x; sxr[fb + 1][j] = v.y;
            sxr[fb + 2][j] = v.z; sxr[fb + 3][j] = v.w;
        }
        __syncthreads();

#pragma unroll 1
        for (int s0 = 0; s0 < CH; s0 += 256) {
            const float* ab = abase + c + s0;
            int jl = s0 + lane * 4;
            // batch 8 LDG.128 for load depth (2 j-steps x 4 rows)
            float4 A0[4], A1[4];
#pragma unroll
            for (int r = 0; r < 4; ++r) A0[r] = __ldcs((const float4*)(ab + r * NN));
#pragma unroll
            for (int r = 0; r < 4; ++r) A1[r] = __ldcs((const float4*)(ab + r * NN + 128));
            // phase 0
            {
                ull ae[4], ao[4];
#pragma unroll
                for (int r = 0; r < 4; ++r) { ae[r] = pk2(A0[r].x, A0[r].y); ao[r] = pk2(A0[r].z, A0[r].w); }
#pragma unroll
                for (int f = 0; f < FF; ++f) {
                    float4 X = *(const float4*)&sxr[f][jl];
                    ull xe = pk2(X.x, X.y), xo = pk2(X.z, X.w);
#pragma unroll
                    for (int r = 0; r < 4; ++r) { fma2(acc[r][f], ae[r], xe); fma2(acc[r][f], ao[r], xo); }
                }
            }
            // phase 1
            {
                ull ae[4], ao[4];
#pragma unroll
                for (int r = 0; r < 4; ++r) { ae[r] = pk2(A1[r].x, A1[r].y); ao[r] = pk2(A1[r].z, A1[r].w); }
#pragma unroll
                for (int f = 0; f < FF; ++f) {
                    float4 X = *(const float4*)&sxr[f][jl + 128];
                    ull xe = pk2(X.x, X.y), xo = pk2(X.z, X.w);
#pragma unroll
                    for (int r = 0; r < 4; ++r) { fma2(acc[r][f], ae[r], xe); fma2(acc[r][f], ao[r], xo); }
                }
            }
        }
    }

    // reduce across lanes
    float v[32];
#pragma unroll
    for (int r = 0; r < 4; ++r)
#pragma unroll
        for (int f = 0; f < FF; ++f) v[r * 8 + f] = hsum2(acc[r][f]);
#pragma unroll
    for (int o = 16; o; o >>= 1)
#pragma unroll
        for (int k = 0; k < 32; ++k) v[k] += __shfl_xor_sync(0xffffffffu, v[k], o);

    if (lane < 4) {
        int row = rowbase + lane;
        float s[8];
#pragma unroll
        for (int f = 0; f < FF; ++f) s[f] = v[lane * 8 + f] + g_corr[row * FF + f];

        float h0[16];
#pragma unroll
        for (int o = 0; o < 16; ++o) {
            float tt = swt[OB0 + o];
#pragma unroll
            for (int i = 0; i < 8; ++i) tt = fmaf(s[i], swt[OW0 + i * 16 + o], tt);
            h0[o] = tanhf(tt);
        }
        float h1[16];
#pragma unroll
        for (int o = 0; o < 16; ++o) {
            float tt = swt[OB1 + o];
#pragma unroll
            for (int i = 0; i < 16; ++i) tt = fmaf(h0[i], swt[OW1 + i * 16 + o], tt);
            h1[o] = tanhf(tt);
        }
        float h2[12];
#pragma unroll
        for (int o = 0; o < 12; ++o) {
            float tt = swt[OB2 + o];
#pragma unroll
            for (int i = 0; i < 16; ++i) tt = fmaf(h1[i], swt[OW2 + i * 12 + o], tt);
            h2[o] = tanhf(tt);
        }
        float h3[8];
#pragma unroll
        for (int o = 0; o < 8; ++o) {
            float tt = swt[OB3 + o];
#pragma unroll
            for (int i = 0; i < 12; ++i) tt = fmaf(h2[i], swt[OW3 + i * 8 + o], tt);
            h3[o] = tanhf(tt);
        }
        float h4[4];
#pragma unroll
        for (int o = 0; o < 4; ++o) {
            float tt = swt[OB4 + o];
#pragma unroll
            for (int i = 0; i < 8; ++i) tt = fmaf(h3[i], swt[OW4 + i * 4 + o], tt);
            h4[o] = tanhf(tt);
        }
        float h5[4];
#pragma unroll
        for (int o = 0; o < 4; ++o) {
            float tt = swt[OB5 + o];
#pragma unroll
            for (int i = 0; i < 4; ++i) tt = fmaf(h4[i], swt[OW5 + i * 4 + o], tt);
            h5[o] = tanhf(tt);
        }
        float z = swt[OB6];
#pragma unroll
        for (int i = 0; i < 4; ++i) z = fmaf(h5[i], swt[OW6 + i], z);
        out[row] = 1.0f / (1.0f + expf(-z));
    }
}

extern "C" void kernel_launch(void* const* d_in, const int* in_sizes, int n_in,
                              void* d_out, int out_size) {
    const float* adj = (const float*)d_in[0];
    const float* x   = (const float*)d_in[1];
    const float* Wfm = (const float*)d_in[2];
    const float* bfm = (const float*)d_in[3];
    const float* Wc1 = (const float*)d_in[4];
    const float* bc1 = (const float*)d_in[5];
    const float* Wp1 = (const float*)d_in[6];
    const float* bp1 = (const float*)d_in[7];
    const float* Wc2 = (const float*)d_in[8];
    const float* bc2 = (const float*)d_in[9];
    const float* Wp2 = (const float*)d_in[10];
    const float* bp2 = (const float*)d_in[11];
    const float* Wc3 = (const float*)d_in[12];
    const float* bc3 = (const float*)d_in[13];
    const float* Wh  = (const float*)d_in[14];
    const float* bh  = (const float*)d_in[15];
    float* out = (float*)d_out;

    void* corr_ptr = nullptr;
    cudaGetSymbolAddress(&corr_ptr, g_corr);
    cudaMemsetAsync(corr_ptr, 0, NN * FF * sizeof(float), 0);

    k_fid<<<NFIDB, FTPB>>>(adj, x);
    k_adj<<<NN / 16, ATPB>>>(adj, x, Wfm, bfm, Wc1, bc1, Wp1, bp1,
                             Wc2, bc2, Wp2, bp2, Wc3, bc3, Wh, bh, out);
}

// round 5
// speedup vs baseline: 1.8829x; 1.0448x over previous
#include <cuda_runtime.h>
#include <math.h>

#define NN 8192
#define FF 8
#define THRESH 0.9f
#define CH 512
#define ATPB 128
#define FTPB 256
#define TILE 128
#define NT (NN / TILE)
#define NFIDB (NT * (NT + 1) / 2)

typedef unsigned long long ull;

__device__ float g_corr[NN * FF];
__device__ float g_sums[NN * FF];

// ---------- packed f32x2 helpers ----------
__device__ __forceinline__ ull pk2(float x, float y) {
    ull r; asm("mov.b64 %0, {%1, %2};" : "=l"(r) : "f"(x), "f"(y)); return r;
}
__device__ __forceinline__ void up2(float& x, float& y, ull v) {
    asm("mov.b64 {%0, %1}, %2;" : "=f"(x), "=f"(y) : "l"(v));
}
__device__ __forceinline__ void fma2(ull& d, ull a, ull b) {
    asm("fma.rn.f32x2 %0, %1, %2, %0;" : "+l"(d) : "l"(a), "l"(b));
}

// ---------- kernel: fidelity hits over upper-triangle 128x128 tiles ----------
__global__ void __launch_bounds__(FTPB) k_fid(const float* __restrict__ adj,
                                              const float* __restrict__ x) {
    __shared__ ull  sIp[TILE * FF];
    __shared__ float sJ[FF][TILE];

    int b = blockIdx.x;
    int ti = (int)(((2 * NT + 1) - sqrtf((float)((2 * NT + 1) * (2 * NT + 1)) - 8.0f * (float)b)) * 0.5f);
    if (ti < 0) ti = 0;
    if (ti > NT - 1) ti = NT - 1;
#define RS(r) ((r) * NT - ((r) * ((r) - 1)) / 2)
    while (ti > 0 && RS(ti) > b) --ti;
    while (RS(ti + 1) <= b) ++ti;
    int tj = ti + (b - RS(ti));
#undef RS

    int t = threadIdx.x;
    {
        int r = t & 127;
        int row = ((t < 128) ? ti : tj) * TILE + r;
        float4 a = *(const float4*)(x + row * FF);
        float4 c = *(const float4*)(x + row * FF + 4);
        float s = a.x*a.x + a.y*a.y + a.z*a.z + a.w*a.w
                + c.x*c.x + c.y*c.y + c.z*c.z + c.w*c.w;
        float inv = 1.0f / (sqrtf(s) + 1e-12f);
        float v[8] = {a.x, a.y, a.z, a.w, c.x, c.y, c.z, c.w};
        if (t < 128) {
#pragma unroll
            for (int f = 0; f < FF; ++f) { float xn = v[f] * inv; sIp[r * FF + f] = pk2(xn, xn); }
        } else {
#pragma unroll
            for (int f = 0; f < FF; ++f) sJ[f][r] = v[f] * inv;
        }
    }
    __syncthreads();

    int w = t >> 5, lane = t & 31;
    int j0 = lane * 4;
    ull xj0[FF], xj1[FF];
#pragma unroll
    for (int f = 0; f < FF; ++f) {
        float4 v = *(const float4*)&sJ[f][j0];
        xj0[f] = pk2(v.x, v.y);
        xj1[f] = pk2(v.z, v.w);
    }
    int gjb = tj * TILE + j0;

#pragma unroll 4
    for (int ii = 0; ii < 16; ++ii) {
        int i = w * 16 + ii;
        ull d0 = 0ULL, d1 = 0ULL;
#pragma unroll
        for (int f = 0; f < FF; ++f) {
            ull xi = sIp[i * FF + f];
            fma2(d0, xi, xj0[f]);
            fma2(d1, xi, xj1[f]);
        }
        float da, db, dc, dd;
        up2(da, db, d0); up2(dc, dd, d1);
        int gi = ti * TILE + i;
        bool h0 = (da * da >= THRESH) && (gi < gjb + 0);
        bool h1 = (db * db >= THRESH) && (gi < gjb + 1);
        bool h2 = (dc * dc >= THRESH) && (gi < gjb + 2);
        bool h3 = (dd * dd >= THRESH) && (gi < gjb + 3);
        if (h0 | h1 | h2 | h3) {
            float4 xia = *(const float4*)(x + gi * FF);
            float4 xib = *(const float4*)(x + gi * FF + 4);
            float xi8[8] = {xia.x, xia.y, xia.z, xia.w, xib.x, xib.y, xib.z, xib.w};
            bool hh[4] = {h0, h1, h2, h3};
#pragma unroll
            for (int k = 0; k < 4; ++k) {
                if (hh[k]) {
                    int gj = gjb + k;
                    float aij = __ldg(adj + (size_t)gi * NN + gj);
                    float aji = __ldg(adj + (size_t)gj * NN + gi);
                    float wi = 1.0f - aij, wj = 1.0f - aji;
#pragma unroll
                    for (int f = 0; f < FF; ++f) {
                        atomicAdd(&g_corr[gi * FF + f], wi * __ldg(x + gj * FF + f));
                        atomicAdd(&g_corr[gj * FF + f], wj * xi8[f]);
                    }
                }
            }
        }
    }
}

// ---------- kernel: stream adjacency with double-buffered prefetch ----------
__global__ void __launch_bounds__(ATPB, 4) k_adj(const float* __restrict__ adj,
                                                 const float* __restrict__ x) {
    __shared__ float sx[FF][CH];   // 16 KB

    int tid = threadIdx.x, warp = tid >> 5, lane = tid & 31;
    int rowbase = blockIdx.x * 16 + warp * 4;
    const float* ap = adj + (size_t)rowbase * NN + lane * 4;

    ull acc[16];   // [r*4+p] : packed (f=2p, f=2p+1) sums
#pragma unroll
    for (int k = 0; k < 16; ++k) acc[k] = 0ULL;

    float4 Abuf[8], Bbuf[8];

#define LOADQ(BUF, OFF) do {                                                    \
    _Pragma("unroll")                                                           \
    for (int r = 0; r < 4; ++r) {                                               \
        BUF[r * 2 + 0] = __ldcs((const float4*)(ap + (size_t)r * NN + (OFF)));  \
        BUF[r * 2 + 1] = __ldcs((const float4*)(ap + (size_t)r * NN + (OFF) + 128)); \
    } } while (0)

#define GETC(V, J) ((J) == 0 ? (V).x : (J) == 1 ? (V).y : (J) == 2 ? (V).z : (V).w)

#define COMPUTE(BUF, BASE) do {                                                 \
    _Pragma("unroll")                                                           \
    for (int ph = 0; ph < 2; ++ph) {                                            \
        int jl = (BASE) + ph * 128 + lane * 4;                                  \
        float4 X0 = *(const float4*)&sx[0][jl];                                 \
        float4 X1 = *(const float4*)&sx[1][jl];                                 \
        float4 X2 = *(const float4*)&sx[2][jl];                                 \
        float4 X3 = *(const float4*)&sx[3][jl];                                 \
        float4 X4 = *(const float4*)&sx[4][jl];                                 \
        float4 X5 = *(const float4*)&sx[5][jl];                                 \
        float4 X6 = *(const float4*)&sx[6][jl];                                 \
        float4 X7 = *(const float4*)&sx[7][jl];                                 \
        _Pragma("unroll")                                                       \
        for (int jj = 0; jj < 4; ++jj) {                                        \
            ull p0 = pk2(GETC(X0, jj), GETC(X1, jj));                           \
            ull p1 = pk2(GETC(X2, jj), GETC(X3, jj));                           \
            ull p2 = pk2(GETC(X4, jj), GETC(X5, jj));                           \
            ull p3 = pk2(GETC(X6, jj), GETC(X7, jj));                           \
            _Pragma("unroll")                                                   \
            for (int r = 0; r < 4; ++r) {                                       \
                float a = GETC(BUF[r * 2 + ph], jj);                            \
                ull ad = pk2(a, a);                                             \
                fma2(acc[r * 4 + 0], ad, p0);                                   \
                fma2(acc[r * 4 + 1], ad, p1);                                   \
                fma2(acc[r * 4 + 2], ad, p2);                                   \
                fma2(acc[r * 4 + 3], ad, p3);                                   \
            } } } } while (0)

    LOADQ(Abuf, 0);   // prime the pipeline

    for (int c = 0; c < NN; c += CH) {
        __syncthreads();
        const float4* xs = (const float4*)x + c * 2;
#pragma unroll
        for (int k = 0; k < 8; ++k) {
            int idx = tid + k * ATPB;
            float4 v = __ldg(xs + idx);
            int j = idx >> 1, fb = (idx & 1) << 2;
            sx[fb + 0][j] = v.x; sx[fb + 1][j] = v.y;
            sx[fb + 2][j] = v.z; sx[fb + 3][j] = v.w;
        }
        __syncthreads();

        LOADQ(Bbuf, c + 256);          // prefetch step 1 of this chunk
        COMPUTE(Abuf, 0);
        if (c + CH < NN) LOADQ(Abuf, c + CH);   // prefetch step 0 of next chunk
        COMPUTE(Bbuf, 256);
    }

    // unpack packed feature-pair sums -> 32 floats, butterfly over j-lanes
    float v[32];
#pragma unroll
    for (int r = 0; r < 4; ++r)
#pragma unroll
        for (int p = 0; p < 4; ++p)
            up2(v[r * 8 + 2 * p], v[r * 8 + 2 * p + 1], acc[r * 4 + p]);
#pragma unroll
    for (int o = 16; o; o >>= 1)
#pragma unroll
        for (int k = 0; k < 32; ++k) v[k] += __shfl_xor_sync(0xffffffffu, v[k], o);

    // lane l holds v[l] = row (l>>3), feature (l&7): one coalesced STG per lane
    g_sums[(rowbase + (lane >> 3)) * FF + (lane & 7)] = v[lane];
}

// ---------- kernel: per-row MLP tail ----------
#define OW0 0
#define OB0 128
#define OW1 144
#define OB1 400
#define OW2 416
#define OB2 608
#define OW3 620
#define OB3 716
#define OW4 724
#define OB4 756
#define OW5 760
#define OB5 776
#define OW6 780
#define OB6 784

__global__ void __launch_bounds__(128) k_post(
    const float* __restrict__ Wfm, const float* __restrict__ bfm,
    const float* __restrict__ Wc1, const float* __restrict__ bc1,
    const float* __restrict__ Wp1, const float* __restrict__ bp1,
    const float* __restrict__ Wc2, const float* __restrict__ bc2,
    const float* __restrict__ Wp2, const float* __restrict__ bp2,
    const float* __restrict__ Wc3, const float* __restrict__ bc3,
    const float* __restrict__ Wh,  const float* __restrict__ bh,
    float* __restrict__ out)
{
    __shared__ float swt[792];
    int tid = threadIdx.x;
    {
        const float* srcs[14] = {Wfm, bfm, Wc1, bc1, Wp1, bp1, Wc2, bc2,
                                 Wp2, bp2, Wc3, bc3, Wh, bh};
        const int szs[14] = {128, 16, 256, 16, 192, 12, 96, 8, 32, 4, 16, 4, 4, 1};
        int off = 0;
        for (int a = 0; a < 14; ++a) {
            for (int k = tid; k < szs[a]; k += 128) swt[off + k] = srcs[a][k];
            off += szs[a];
        }
    }
    __syncthreads();

    int row = blockIdx.x * 128 + tid;
    float s[8];
#pragma unroll
    for (int f = 0; f < FF; ++f) s[f] = g_sums[row * FF + f] + g_corr[row * FF + f];

    float h0[16];
#pragma unroll
    for (int o = 0; o < 16; ++o) {
        float t = swt[OB0 + o];
#pragma unroll
        for (int i = 0; i < 8; ++i) t = fmaf(s[i], swt[OW0 + i * 16 + o], t);
        h0[o] = tanhf(t);
    }
    float h1[16];
#pragma unroll
    for (int o = 0; o < 16; ++o) {
        float t = swt[OB1 + o];
#pragma unroll
        for (int i = 0; i < 16; ++i) t = fmaf(h0[i], swt[OW1 + i * 16 + o], t);
        h1[o] = tanhf(t);
    }
    float h2[12];
#pragma unroll
    for (int o = 0; o < 12; ++o) {
        float t = swt[OB2 + o];
#pragma unroll
        for (int i = 0; i < 16; ++i) t = fmaf(h1[i], swt[OW2 + i * 12 + o], t);
        h2[o] = tanhf(t);
    }
    float h3[8];
#pragma unroll
    for (int o = 0; o < 8; ++o) {
        float t = swt[OB3 + o];
#pragma unroll
        for (int i = 0; i < 12; ++i) t = fmaf(h2[i], swt[OW3 + i * 8 + o], t);
        h3[o] = tanhf(t);
    }
    float h4[4];
#pragma unroll
    for (int o = 0; o < 4; ++o) {
        float t = swt[OB4 + o];
#pragma unroll
        for (int i = 0; i < 8; ++i) t = fmaf(h3[i], swt[OW4 + i * 4 + o], t);
        h4[o] = tanhf(t);
    }
    float h5[4];
#pragma unroll
    for (int o = 0; o < 4; ++o) {
        float t = swt[OB5 + o];
#pragma unroll
        for (int i = 0; i < 4; ++i) t = fmaf(h4[i], swt[OW5 + i * 4 + o], t);
        h5[o] = tanhf(t);
    }
    float z = swt[OB6];
#pragma unroll
    for (int i = 0; i < 4; ++i) z = fmaf(h5[i], swt[OW6 + i], z);
    out[row] = 1.0f / (1.0f + expf(-z));
}

extern "C" void kernel_launch(void* const* d_in, const int* in_sizes, int n_in,
                              void* d_out, int out_size) {
    const float* adj = (const float*)d_in[0];
    const float* x   = (const float*)d_in[1];
    const float* Wfm = (const float*)d_in[2];
    const float* bfm = (const float*)d_in[3];
    const float* Wc1 = (const float*)d_in[4];
    const float* bc1 = (const float*)d_in[5];
    const float* Wp1 = (const float*)d_in[6];
    const float* bp1 = (const float*)d_in[7];
    const float* Wc2 = (const float*)d_in[8];
    const float* bc2 = (const float*)d_in[9];
    const float* Wp2 = (const float*)d_in[10];
    const float* bp2 = (const float*)d_in[11];
    const float* Wc3 = (const float*)d_in[12];
    const float* bc3 = (const float*)d_in[13];
    const float* Wh  = (const float*)d_in[14];
    const float* bh  = (const float*)d_in[15];
    float* out = (float*)d_out;

    static cudaStream_t s2 = nullptr;
    static cudaEvent_t e0 = nullptr, e1 = nullptr;
    if (s2 == nullptr) {
        cudaStreamCreateWithFlags(&s2, cudaStreamNonBlocking);
        cudaEventCreateWithFlags(&e0, cudaEventDisableTiming);
        cudaEventCreateWithFlags(&e1, cudaEventDisableTiming);
    }

    void* corr_ptr = nullptr;
    cudaGetSymbolAddress(&corr_ptr, g_corr);

    // fork: fid branch (memset + k_fid) runs concurrently with k_adj
    cudaEventRecord(e0, 0);
    cudaStreamWaitEvent(s2, e0, 0);
    cudaMemsetAsync(corr_ptr, 0, NN * FF * sizeof(float), s2);
    k_fid<<<NFIDB, FTPB, 0, s2>>>(adj, x);
    cudaEventRecord(e1, s2);

    k_adj<<<NN / 16, ATPB>>>(adj, x);

    cudaStreamWaitEvent(0, e1, 0);   // join before k_post reads g_corr
    k_post<<<NN / 128, 128>>>(Wfm, bfm, Wc1, bc1, Wp1, bp1, Wc2, bc2,
                              Wp2, bp2, Wc3, bc3, Wh, bh, out);
}

// round 6
// speedup vs baseline: 1.9720x; 1.0474x over previous
#include <cuda_runtime.h>
#include <math.h>

#define NN 8192
#define FF 8
#define THRESH 0.9f
#define CH 512
#define ATPB 128
#define FTPB 256
#define TILE 128
#define NT (NN / TILE)
#define NFIDB (NT * (NT + 1) / 2)

typedef unsigned long long ull;

__device__ float g_corr[NN * FF];
__device__ float g_sums[NN * FF];
__device__ float g_xn[NN * FF];     // normalized features, row-major

// ---------- packed f32x2 helpers ----------
__device__ __forceinline__ ull pk2(float x, float y) {
    ull r; asm("mov.b64 %0, {%1, %2};" : "=l"(r) : "f"(x), "f"(y)); return r;
}
__device__ __forceinline__ void up2(float& x, float& y, ull v) {
    asm("mov.b64 {%0, %1}, %2;" : "=f"(x), "=f"(y) : "l"(v));
}
__device__ __forceinline__ void fma2(ull& d, ull a, ull b) {
    asm("fma.rn.f32x2 %0, %1, %2, %0;" : "+l"(d) : "l"(a), "l"(b));
}

// ---------- kernel: normalize features (coalesced, row-major only) ----------
__global__ void __launch_bounds__(128) k_prep(const float* __restrict__ x) {
    int i = blockIdx.x * 128 + threadIdx.x;
    float4 a = *(const float4*)(x + i * FF);
    float4 b = *(const float4*)(x + i * FF + 4);
    float s = a.x*a.x + a.y*a.y + a.z*a.z + a.w*a.w
            + b.x*b.x + b.y*b.y + b.z*b.z + b.w*b.w;
    float inv = 1.0f / (sqrtf(s) + 1e-12f);
    a.x *= inv; a.y *= inv; a.z *= inv; a.w *= inv;
    b.x *= inv; b.y *= inv; b.z *= inv; b.w *= inv;
    *(float4*)(g_xn + i * FF)     = a;
    *(float4*)(g_xn + i * FF + 4) = b;
}

// ---------- kernel: fidelity hits over upper-triangle 128x128 tiles ----------
__global__ void __launch_bounds__(FTPB) k_fid(const float* __restrict__ adj,
                                              const float* __restrict__ x) {
    __shared__ ull  sIp[TILE * FF];
    __shared__ float sJ[FF][TILE];

    int b = blockIdx.x;
    int ti = (int)(((2 * NT + 1) - sqrtf((float)((2 * NT + 1) * (2 * NT + 1)) - 8.0f * (float)b)) * 0.5f);
    if (ti < 0) ti = 0;
    if (ti > NT - 1) ti = NT - 1;
#define RS(r) ((r) * NT - ((r) * ((r) - 1)) / 2)
    while (ti > 0 && RS(ti) > b) --ti;
    while (RS(ti + 1) <= b) ++ti;
    int tj = ti + (b - RS(ti));
#undef RS

    int t = threadIdx.x;
    {   // stage normalized rows: threads 0-127 -> I tile, 128-255 -> J tile
        int r = t & 127;
        int row = ((t < 128) ? ti : tj) * TILE + r;
        float4 a = *(const float4*)(g_xn + row * FF);
        float4 c = *(const float4*)(g_xn + row * FF + 4);
        float v[8] = {a.x, a.y, a.z, a.w, c.x, c.y, c.z, c.w};
        if (t < 128) {
#pragma unroll
            for (int f = 0; f < FF; ++f) sIp[r * FF + f] = pk2(v[f], v[f]);
        } else {
#pragma unroll
            for (int f = 0; f < FF; ++f) sJ[f][r] = v[f];
        }
    }
    __syncthreads();

    int w = t >> 5, lane = t & 31;
    int j0 = lane * 4;
    ull xj0[FF], xj1[FF];
#pragma unroll
    for (int f = 0; f < FF; ++f) {
        float4 v = *(const float4*)&sJ[f][j0];
        xj0[f] = pk2(v.x, v.y);
        xj1[f] = pk2(v.z, v.w);
    }
    int gjb = tj * TILE + j0;

#pragma unroll 8
    for (int ii = 0; ii < 16; ++ii) {
        int i = w * 16 + ii;
        ull d0 = 0ULL, d1 = 0ULL;
#pragma unroll
        for (int f = 0; f < FF; ++f) {
            ull xi = sIp[i * FF + f];     // LDS.64 broadcast
            fma2(d0, xi, xj0[f]);
            fma2(d1, xi, xj1[f]);
        }
        float da, db, dc, dd;
        up2(da, db, d0); up2(dc, dd, d1);
        int gi = ti * TILE + i;
        bool h0 = (da * da >= THRESH) && (gi < gjb + 0);
        bool h1 = (db * db >= THRESH) && (gi < gjb + 1);
        bool h2 = (dc * dc >= THRESH) && (gi < gjb + 2);
        bool h3 = (dd * dd >= THRESH) && (gi < gjb + 3);
        if (h0 | h1 | h2 | h3) {          // rare
            float4 xia = *(const float4*)(x + gi * FF);
            float4 xib = *(const float4*)(x + gi * FF + 4);
            float xi8[8] = {xia.x, xia.y, xia.z, xia.w, xib.x, xib.y, xib.z, xib.w};
            bool hh[4] = {h0, h1, h2, h3};
#pragma unroll
            for (int k = 0; k < 4; ++k) {
                if (hh[k]) {
                    int gj = gjb + k;
                    float aij = __ldg(adj + (size_t)gi * NN + gj);
                    float aji = __ldg(adj + (size_t)gj * NN + gi);
                    float wi = 1.0f - aij, wj = 1.0f - aji;
#pragma unroll
                    for (int f = 0; f < FF; ++f) {
                        atomicAdd(&g_corr[gi * FF + f], wi * __ldg(x + gj * FF + f));
                        atomicAdd(&g_corr[gj * FF + f], wj * xi8[f]);
                    }
                }
            }
        }
    }
}

// ---------- kernel: stream adjacency with double-buffered prefetch ----------
__global__ void __launch_bounds__(ATPB, 4) k_adj(const float* __restrict__ adj,
                                                 const float* __restrict__ x) {
    __shared__ float sx[FF][CH];   // 16 KB

    int tid = threadIdx.x, warp = tid >> 5, lane = tid & 31;
    int rowbase = blockIdx.x * 16 + warp * 4;
    const float* ap = adj + (size_t)rowbase * NN + lane * 4;

    ull acc[16];   // [r*4+p] : packed (f=2p, f=2p+1) sums
#pragma unroll
    for (int k = 0; k < 16; ++k) acc[k] = 0ULL;

    float4 Abuf[8], Bbuf[8];

#define LOADQ(BUF, OFF) do {                                                    \
    _Pragma("unroll")                                                           \
    for (int r = 0; r < 4; ++r) {                                               \
        BUF[r * 2 + 0] = __ldcs((const float4*)(ap + (size_t)r * NN + (OFF)));  \
        BUF[r * 2 + 1] = __ldcs((const float4*)(ap + (size_t)r * NN + (OFF) + 128)); \
    } } while (0)

#define GETC(V, J) ((J) == 0 ? (V).x : (J) == 1 ? (V).y : (J) == 2 ? (V).z : (V).w)

#define COMPUTE(BUF, BASE) do {                                                 \
    _Pragma("unroll")                                                           \
    for (int ph = 0; ph < 2; ++ph) {                                            \
        int jl = (BASE) + ph * 128 + lane * 4;                                  \
        float4 X0 = *(const float4*)&sx[0][jl];                                 \
        float4 X1 = *(const float4*)&sx[1][jl];                                 \
        float4 X2 = *(const float4*)&sx[2][jl];                                 \
        float4 X3 = *(const float4*)&sx[3][jl];                                 \
        float4 X4 = *(const float4*)&sx[4][jl];                                 \
        float4 X5 = *(const float4*)&sx[5][jl];                                 \
        float4 X6 = *(const float4*)&sx[6][jl];                                 \
        float4 X7 = *(const float4*)&sx[7][jl];                                 \
        _Pragma("unroll")                                                       \
        for (int jj = 0; jj < 4; ++jj) {                                        \
            ull p0 = pk2(GETC(X0, jj), GETC(X1, jj));                           \
            ull p1 = pk2(GETC(X2, jj), GETC(X3, jj));                           \
            ull p2 = pk2(GETC(X4, jj), GETC(X5, jj));                           \
            ull p3 = pk2(GETC(X6, jj), GETC(X7, jj));                           \
            _Pragma("unroll")                                                   \
            for (int r = 0; r < 4; ++r) {                                       \
                float a = GETC(BUF[r * 2 + ph], jj);                            \
                ull ad = pk2(a, a);                                             \
                fma2(acc[r * 4 + 0], ad, p0);                                   \
                fma2(acc[r * 4 + 1], ad, p1);                                   \
                fma2(acc[r * 4 + 2], ad, p2);                                   \
                fma2(acc[r * 4 + 3], ad, p3);                                   \
            } } } } while (0)

    LOADQ(Abuf, 0);   // prime

    for (int c = 0; c < NN; c += CH) {
        __syncthreads();
        const float4* xs = (const float4*)x + c * 2;
#pragma unroll
        for (int k = 0; k < 8; ++k) {
            int idx = tid + k * ATPB;
            float4 v = __ldg(xs + idx);
            int j = idx >> 1, fb = (idx & 1) << 2;
            sx[fb + 0][j] = v.x; sx[fb + 1][j] = v.y;
            sx[fb + 2][j] = v.z; sx[fb + 3][j] = v.w;
        }
        __syncthreads();

        LOADQ(Bbuf, c + 256);
        COMPUTE(Abuf, 0);
        if (c + CH < NN) LOADQ(Abuf, c + CH);
        COMPUTE(Bbuf, 256);
    }

    float v[32];
#pragma unroll
    for (int r = 0; r < 4; ++r)
#pragma unroll
        for (int p = 0; p < 4; ++p)
            up2(v[r * 8 + 2 * p], v[r * 8 + 2 * p + 1], acc[r * 4 + p]);
#pragma unroll
    for (int o = 16; o; o >>= 1)
#pragma unroll
        for (int k = 0; k < 32; ++k) v[k] += __shfl_xor_sync(0xffffffffu, v[k], o);

    g_sums[(rowbase + (lane >> 3)) * FF + (lane & 7)] = v[lane];
}

// ---------- kernel: per-row MLP tail ----------
#define OW0 0
#define OB0 128
#define OW1 144
#define OB1 400
#define OW2 416
#define OB2 608
#define OW3 620
#define OB3 716
#define OW4 724
#define OB4 756
#define OW5 760
#define OB5 776
#define OW6 780
#define OB6 784

__global__ void __launch_bounds__(128) k_post(
    const float* __restrict__ Wfm, const float* __restrict__ bfm,
    const float* __restrict__ Wc1, const float* __restrict__ bc1,
    const float* __restrict__ Wp1, const float* __restrict__ bp1,
    const float* __restrict__ Wc2, const float* __restrict__ bc2,
    const float* __restrict__ Wp2, const float* __restrict__ bp2,
    const float* __restrict__ Wc3, const float* __restrict__ bc3,
    const float* __restrict__ Wh,  const float* __restrict__ bh,
    float* __restrict__ out)
{
    __shared__ float swt[792];
    int tid = threadIdx.x;
    {
        const float* srcs[14] = {Wfm, bfm, Wc1, bc1, Wp1, bp1, Wc2, bc2,
                                 Wp2, bp2, Wc3, bc3, Wh, bh};
        const int szs[14] = {128, 16, 256, 16, 192, 12, 96, 8, 32, 4, 16, 4, 4, 1};
        int off = 0;
        for (int a = 0; a < 14; ++a) {
            for (int k = tid; k < szs[a]; k += 128) swt[off + k] = srcs[a][k];
            off += szs[a];
        }
    }
    __syncthreads();

    int row = blockIdx.x * 128 + tid;
    float s[8];
#pragma unroll
    for (int f = 0; f < FF; ++f) s[f] = g_sums[row * FF + f] + g_corr[row * FF + f];

    float h0[16];
#pragma unroll
    for (int o = 0; o < 16; ++o) {
        float t = swt[OB0 + o];
#pragma unroll
        for (int i = 0; i < 8; ++i) t = fmaf(s[i], swt[OW0 + i * 16 + o], t);
        h0[o] = tanhf(t);
    }
    float h1[16];
#pragma unroll
    for (int o = 0; o < 16; ++o) {
        float t = swt[OB1 + o];
#pragma unroll
        for (int i = 0; i < 16; ++i) t = fmaf(h0[i], swt[OW1 + i * 16 + o], t);
        h1[o] = tanhf(t);
    }
    float h2[12];
#pragma unroll
    for (int o = 0; o < 12; ++o) {
        float t = swt[OB2 + o];
#pragma unroll
        for (int i = 0; i < 16; ++i) t = fmaf(h1[i], swt[OW2 + i * 12 + o], t);
        h2[o] = tanhf(t);
    }
    float h3[8];
#pragma unroll
    for (int o = 0; o < 8; ++o) {
        float t = swt[OB3 + o];
#pragma unroll
        for (int i = 0; i < 12; ++i) t = fmaf(h2[i], swt[OW3 + i * 8 + o], t);
        h3[o] = tanhf(t);
    }
    float h4[4];
#pragma unroll
    for (int o = 0; o < 4; ++o) {
        float t = swt[OB4 + o];
#pragma unroll
        for (int i = 0; i < 8; ++i) t = fmaf(h3[i], swt[OW4 + i * 4 + o], t);
        h4[o] = tanhf(t);
    }
    float h5[4];
#pragma unroll
    for (int o = 0; o < 4; ++o) {
        float t = swt[OB5 + o];
#pragma unroll
        for (int i = 0; i < 4; ++i) t = fmaf(h4[i], swt[OW5 + i * 4 + o], t);
        h5[o] = tanhf(t);
    }
    float z = swt[OB6];
#pragma unroll
    for (int i = 0; i < 4; ++i) z = fmaf(h5[i], swt[OW6 + i], z);
    out[row] = 1.0f / (1.0f + expf(-z));
}

extern "C" void kernel_launch(void* const* d_in, const int* in_sizes, int n_in,
                              void* d_out, int out_size) {
    const float* adj = (const float*)d_in[0];
    const float* x   = (const float*)d_in[1];
    const float* Wfm = (const float*)d_in[2];
    const float* bfm = (const float*)d_in[3];
    const float* Wc1 = (const float*)d_in[4];
    const float* bc1 = (const float*)d_in[5];
    const float* Wp1 = (const float*)d_in[6];
    const float* bp1 = (const float*)d_in[7];
    const float* Wc2 = (const float*)d_in[8];
    const float* bc2 = (const float*)d_in[9];
    const float* Wp2 = (const float*)d_in[10];
    const float* bp2 = (const float*)d_in[11];
    const float* Wc3 = (const float*)d_in[12];
    const float* bc3 = (const float*)d_in[13];
    const float* Wh  = (const float*)d_in[14];
    const float* bh  = (const float*)d_in[15];
    float* out = (float*)d_out;

    static cudaStream_t s2 = nullptr;
    static cudaEvent_t e0 = nullptr, e1 = nullptr;
    if (s2 == nullptr) {
        cudaStreamCreateWithFlags(&s2, cudaStreamNonBlocking);
        cudaEventCreateWithFlags(&e0, cudaEventDisableTiming);
        cudaEventCreateWithFlags(&e1, cudaEventDisableTiming);
    }

    void* corr_ptr = nullptr;
    cudaGetSymbolAddress(&corr_ptr, g_corr);

    // fork point BEFORE k_adj, but k_adj is issued first so its 512 blocks
    // (fully resident at 4/SM) own the SMs; fid branch time-shares idle slots.
    cudaEventRecord(e0, 0);
    k_adj<<<NN / 16, ATPB>>>(adj, x);

    cudaStreamWaitEvent(s2, e0, 0);
    cudaMemsetAsync(corr_ptr, 0, NN * FF * sizeof(float), s2);
    k_prep<<<NN / 128, 128, 0, s2>>>(x);
    k_fid<<<NFIDB, FTPB, 0, s2>>>(adj, x);
    cudaEventRecord(e1, s2);

    cudaStreamWaitEvent(0, e1, 0);   // join before k_post reads g_corr
    k_post<<<NN / 128, 128>>>(Wfm, bfm, Wc1, bc1, Wp1, bp1, Wc2, bc2,
                              Wp2, bp2, Wc3, bc3, Wh, bh, out);
}

// round 8
// speedup vs baseline: 1.9821x; 1.0051x over previous
#include <cuda_runtime.h>
#include <math.h>

#define NN 8192
#define FF 8
#define THRESH 0.9f
#define CH 512
#define ATPB 128
#define FTPB 256
#define TILE 128
#define NT (NN / TILE)
#define NFIDB (NT * (NT + 1) / 2)

typedef unsigned long long ull;

__device__ float g_corr[NN * FF];
__device__ float g_sums[NN * FF];
__device__ float g_xn[NN * FF];     // normalized features, row-major

// ---------- packed f32x2 helpers ----------
__device__ __forceinline__ ull pk2(float x, float y) {
    ull r; asm("mov.b64 %0, {%1, %2};" : "=l"(r) : "f"(x), "f"(y)); return r;
}
__device__ __forceinline__ void up2(float& x, float& y, ull v) {
    asm("mov.b64 {%0, %1}, %2;" : "=f"(x), "=f"(y) : "l"(v));
}
__device__ __forceinline__ void fma2(ull& d, ull a, ull b) {
    asm("fma.rn.f32x2 %0, %1, %2, %0;" : "+l"(d) : "l"(a), "l"(b));
}

// ---------- kernel: normalize features (coalesced, row-major only) ----------
__global__ void __launch_bounds__(128) k_prep(const float* __restrict__ x) {
    int i = blockIdx.x * 128 + threadIdx.x;
    float4 a = *(const float4*)(x + i * FF);
    float4 b = *(const float4*)(x + i * FF + 4);
    float s = a.x*a.x + a.y*a.y + a.z*a.z + a.w*a.w
            + b.x*b.x + b.y*b.y + b.z*b.z + b.w*b.w;
    float inv = 1.0f / (sqrtf(s) + 1e-12f);
    a.x *= inv; a.y *= inv; a.z *= inv; a.w *= inv;
    b.x *= inv; b.y *= inv; b.z *= inv; b.w *= inv;
    *(float4*)(g_xn + i * FF)     = a;
    *(float4*)(g_xn + i * FF + 4) = b;
}

// ---------- kernel: fidelity hits over upper-triangle 128x128 tiles ----------
__global__ void __launch_bounds__(FTPB) k_fid(const float* __restrict__ adj,
                                              const float* __restrict__ x) {
    __shared__ ull  sIp[TILE * FF];
    __shared__ float sJ[FF][TILE];

    int b = blockIdx.x;
    int ti = (int)(((2 * NT + 1) - sqrtf((float)((2 * NT + 1) * (2 * NT + 1)) - 8.0f * (float)b)) * 0.5f);
    if (ti < 0) ti = 0;
    if (ti > NT - 1) ti = NT - 1;
#define RS(r) ((r) * NT - ((r) * ((r) - 1)) / 2)
    while (ti > 0 && RS(ti) > b) --ti;
    while (RS(ti + 1) <= b) ++ti;
    int tj = ti + (b - RS(ti));
#undef RS

    int t = threadIdx.x;
    {   // stage normalized rows: threads 0-127 -> I tile, 128-255 -> J tile
        int r = t & 127;
        int row = ((t < 128) ? ti : tj) * TILE + r;
        float4 a = *(const float4*)(g_xn + row * FF);
        float4 c = *(const float4*)(g_xn + row * FF + 4);
        float v[8] = {a.x, a.y, a.z, a.w, c.x, c.y, c.z, c.w};
        if (t < 128) {
#pragma unroll
            for (int f = 0; f < FF; ++f) sIp[r * FF + f] = pk2(v[f], v[f]);
        } else {
#pragma unroll
            for (int f = 0; f < FF; ++f) sJ[f][r] = v[f];
        }
    }
    __syncthreads();

    int w = t >> 5, lane = t & 31;
    int j0 = lane * 4;
    ull xj0[FF], xj1[FF];
#pragma unroll
    for (int f = 0; f < FF; ++f) {
        float4 v = *(const float4*)&sJ[f][j0];
        xj0[f] = pk2(v.x, v.y);
        xj1[f] = pk2(v.z, v.w);
    }
    int gjb = tj * TILE + j0;

#pragma unroll 8
    for (int ii = 0; ii < 16; ++ii) {
        int i = w * 16 + ii;
        ull d0 = 0ULL, d1 = 0ULL;
#pragma unroll
        for (int f = 0; f < FF; ++f) {
            ull xi = sIp[i * FF + f];     // LDS.64 broadcast
            fma2(d0, xi, xj0[f]);
            fma2(d1, xi, xj1[f]);
        }
        float da, db, dc, dd;
        up2(da, db, d0); up2(dc, dd, d1);
        int gi = ti * TILE + i;
        bool h0 = (da * da >= THRESH) && (gi < gjb + 0);
        bool h1 = (db * db >= THRESH) && (gi < gjb + 1);
        bool h2 = (dc * dc >= THRESH) && (gi < gjb + 2);
        bool h3 = (dd * dd >= THRESH) && (gi < gjb + 3);
        if (h0 | h1 | h2 | h3) {          // rare
            float4 xia = *(const float4*)(x + gi * FF);
            float4 xib = *(const float4*)(x + gi * FF + 4);
            float xi8[8] = {xia.x, xia.y, xia.z, xia.w, xib.x, xib.y, xib.z, xib.w};
            bool hh[4] = {h0, h1, h2, h3};
#pragma unroll
            for (int k = 0; k < 4; ++k) {
                if (hh[k]) {
                    int gj = gjb + k;
                    float aij = __ldg(adj + (size_t)gi * NN + gj);
                    float aji = __ldg(adj + (size_t)gj * NN + gi);
                    float wi = 1.0f - aij, wj = 1.0f - aji;
#pragma unroll
                    for (int f = 0; f < FF; ++f) {
                        atomicAdd(&g_corr[gi * FF + f], wi * __ldg(x + gj * FF + f));
                        atomicAdd(&g_corr[gj * FF + f], wj * xi8[f]);
                    }
                }
            }
        }
    }
}

// ---------- kernel: stream adjacency with double-buffered prefetch ----------
__global__ void __launch_bounds__(ATPB, 4) k_adj(const float* __restrict__ adj,
                                                 const float* __restrict__ x) {
    __shared__ float sx[FF][CH];   // 16 KB

    int tid = threadIdx.x, warp = tid >> 5, lane = tid & 31;
    int rowbase = blockIdx.x * 16 + warp * 4;
    const float* ap = adj + (size_t)rowbase * NN + lane * 4;

    ull acc[16];   // [r*4+p] : packed (f=2p, f=2p+1) sums
#pragma unroll
    for (int k = 0; k < 16; ++k) acc[k] = 0ULL;

    float4 Abuf[8], Bbuf[8];

#define LOADQ(BUF, OFF) do {                                                    \
    _Pragma("unroll")                                                           \
    for (int r = 0; r < 4; ++r) {                                               \
        BUF[r * 2 + 0] = __ldcs((const float4*)(ap + (size_t)r * NN + (OFF)));  \
        BUF[r * 2 + 1] = __ldcs((const float4*)(ap + (size_t)r * NN + (OFF) + 128)); \
    } } while (0)

#define GETC(V, J) ((J) == 0 ? (V).x : (J) == 1 ? (V).y : (J) == 2 ? (V).z : (V).w)

#define COMPUTE(BUF, BASE) do {                                                 \
    _Pragma("unroll")                                                           \
    for (int ph = 0; ph < 2; ++ph) {                                            \
        int jl = (BASE) + ph * 128 + lane * 4;                                  \
        float4 X0 = *(const float4*)&sx[0][jl];                                 \
        float4 X1 = *(const float4*)&sx[1][jl];                                 \
        float4 X2 = *(const float4*)&sx[2][jl];                                 \
        float4 X3 = *(const float4*)&sx[3][jl];                                 \
        float4 X4 = *(const float4*)&sx[4][jl];                                 \
        float4 X5 = *(const float4*)&sx[5][jl];                                 \
        float4 X6 = *(const float4*)&sx[6][jl];                                 \
        float4 X7 = *(const float4*)&sx[7][jl];                                 \
        _Pragma("unroll")                                                       \
        for (int jj = 0; jj < 4; ++jj) {                                        \
            ull p0 = pk2(GETC(X0, jj), GETC(X1, jj));                           \
            ull p1 = pk2(GETC(X2, jj), GETC(X3, jj));                           \
            ull p2 = pk2(GETC(X4, jj), GETC(X5, jj));                           \
            ull p3 = pk2(GETC(X6, jj), GETC(X7, jj));                           \
            _Pragma("unroll")                                                   \
            for (int r = 0; r < 4; ++r) {                                       \
                float a = GETC(BUF[r * 2 + ph], jj);                            \
                ull ad = pk2(a, a);                                             \
                fma2(acc[r * 4 + 0], ad, p0);                                   \
                fma2(acc[r * 4 + 1], ad, p1);                                   \
                fma2(acc[r * 4 + 2], ad, p2);                                   \
                fma2(acc[r * 4 + 3], ad, p3);                                   \
            } } } } while (0)

    LOADQ(Abuf, 0);   // prime

    for (int c = 0; c < NN; c += CH) {
        __syncthreads();
        const float4* xs = (const float4*)x + c * 2;
#pragma unroll
        for (int k = 0; k < 8; ++k) {
            int idx = tid + k * ATPB;
            float4 v = __ldg(xs + idx);
            int j = idx >> 1, fb = (idx & 1) << 2;
            sx[fb + 0][j] = v.x; sx[fb + 1][j] = v.y;
            sx[fb + 2][j] = v.z; sx[fb + 3][j] = v.w;
        }
        __syncthreads();

        LOADQ(Bbuf, c + 256);
        COMPUTE(Abuf, 0);
        if (c + CH < NN) LOADQ(Abuf, c + CH);
        COMPUTE(Bbuf, 256);
    }

    float v[32];
#pragma unroll
    for (int r = 0; r < 4; ++r)
#pragma unroll
        for (int p = 0; p < 4; ++p)
            up2(v[r * 8 + 2 * p], v[r * 8 + 2 * p + 1], acc[r * 4 + p]);
#pragma unroll
    for (int o = 16; o; o >>= 1)
#pragma unroll
        for (int k = 0; k < 32; ++k) v[k] += __shfl_xor_sync(0xffffffffu, v[k], o);

    g_sums[(rowbase + (lane >> 3)) * FF + (lane & 7)] = v[lane];
}

// ---------- kernel: per-row MLP tail ----------
#define OW0 0
#define OB0 128
#define OW1 144
#define OB1 400
#define OW2 416
#define OB2 608
#define OW3 620
#define OB3 716
#define OW4 724
#define OB4 756
#define OW5 760
#define OB5 776
#define OW6 780
#define OB6 784

__global__ void __launch_bounds__(128) k_post(
    const float* __restrict__ Wfm, const float* __restrict__ bfm,
    const float* __restrict__ Wc1, const float* __restrict__ bc1,
    const float* __restrict__ Wp1, const float* __restrict__ bp1,
    const float* __restrict__ Wc2, const float* __restrict__ bc2,
    const float* __restrict__ Wp2, const float* __restrict__ bp2,
    const float* __restrict__ Wc3, const float* __restrict__ bc3,
    const float* __restrict__ Wh,  const float* __restrict__ bh,
    float* __restrict__ out)
{
    __shared__ float swt[792];
    int tid = threadIdx.x;
    {
        const float* srcs[14] = {Wfm, bfm, Wc1, bc1, Wp1, bp1, Wc2, bc2,
                                 Wp2, bp2, Wc3, bc3, Wh, bh};
        const int szs[14] = {128, 16, 256, 16, 192, 12, 96, 8, 32, 4, 16, 4, 4, 1};
        int off = 0;
        for (int a = 0; a < 14; ++a) {
            for (int k = tid; k < szs[a]; k += 128) swt[off + k] = srcs[a][k];
            off += szs[a];
        }
    }
    __syncthreads();

    int row = blockIdx.x * 128 + tid;
    float s[8];
#pragma unroll
    for (int f = 0; f < FF; ++f) s[f] = g_sums[row * FF + f] + g_corr[row * FF + f];

    float h0[16];
#pragma unroll
    for (int o = 0; o < 16; ++o) {
        float t = swt[OB0 + o];
#pragma unroll
        for (int i = 0; i < 8; ++i) t = fmaf(s[i], swt[OW0 + i * 16 + o], t);
        h0[o] = tanhf(t);
    }
    float h1[16];
#pragma unroll
    for (int o = 0; o < 16; ++o) {
        float t = swt[OB1 + o];
#pragma unroll
        for (int i = 0; i < 16; ++i) t = fmaf(h0[i], swt[OW1 + i * 16 + o], t);
        h1[o] = tanhf(t);
    }
    float h2[12];
#pragma unroll
    for (int o = 0; o < 12; ++o) {
        float t = swt[OB2 + o];
#pragma unroll
        for (int i = 0; i < 16; ++i) t = fmaf(h1[i], swt[OW2 + i * 12 + o], t);
        h2[o] = tanhf(t);
    }
    float h3[8];
#pragma unroll
    for (int o = 0; o < 8; ++o) {
        float t = swt[OB3 + o];
#pragma unroll
        for (int i = 0; i < 12; ++i) t = fmaf(h2[i], swt[OW3 + i * 8 + o], t);
        h3[o] = tanhf(t);
    }
    float h4[4];
#pragma unroll
    for (int o = 0; o < 4; ++o) {
        float t = swt[OB4 + o];
#pragma unroll
        for (int i = 0; i < 8; ++i) t = fmaf(h3[i], swt[OW4 + i * 4 + o], t);
        h4[o] = tanhf(t);
    }
    float h5[4];
#pragma unroll
    for (int o = 0; o < 4; ++o) {
        float t = swt[OB5 + o];
#pragma unroll
        for (int i = 0; i < 4; ++i) t = fmaf(h4[i], swt[OW5 + i * 4 + o], t);
        h5[o] = tanhf(t);
    }
    float z = swt[OB6];
#pragma unroll
    for (int i = 0; i < 4; ++i) z = fmaf(h5[i], swt[OW6 + i], z);
    out[row] = 1.0f / (1.0f + expf(-z));
}

extern "C" void kernel_launch(void* const* d_in, const int* in_sizes, int n_in,
                              void* d_out, int out_size) {
    const float* adj = (const float*)d_in[0];
    const float* x   = (const float*)d_in[1];
    const float* Wfm = (const float*)d_in[2];
    const float* bfm = (const float*)d_in[3];
    const float* Wc1 = (const float*)d_in[4];
    const float* bc1 = (const float*)d_in[5];
    const float* Wp1 = (const float*)d_in[6];
    const float* bp1 = (const float*)d_in[7];
    const float* Wc2 = (const float*)d_in[8];
    const float* bc2 = (const float*)d_in[9];
    const float* Wp2 = (const float*)d_in[10];
    const float* bp2 = (const float*)d_in[11];
    const float* Wc3 = (const float*)d_in[12];
    const float* bc3 = (const float*)d_in[13];
    const float* Wh  = (const float*)d_in[14];
    const float* bh  = (const float*)d_in[15];
    float* out = (float*)d_out;

    static cudaStream_t s2 = nullptr;
    static cudaEvent_t e0 = nullptr, e1 = nullptr;
    if (s2 == nullptr) {
        cudaStreamCreateWithFlags(&s2, cudaStreamNonBlocking);
        cudaEventCreateWithFlags(&e0, cudaEventDisableTiming);
        cudaEventCreateWithFlags(&e1, cudaEventDisableTiming);
    }

    void* corr_ptr = nullptr;
    cudaGetSymbolAddress(&corr_ptr, g_corr);

    // fork point BEFORE k_adj, but k_adj is issued first so its 512 blocks
    // (fully resident at 4/SM) own the SMs; fid branch time-shares idle slots.
    cudaEventRecord(e0, 0);
    k_adj<<<NN / 16, ATPB>>>(adj, x);

    cudaStreamWaitEvent(s2, e0, 0);
    cudaMemsetAsync(corr_ptr, 0, NN * FF * sizeof(float), s2);
    k_prep<<<NN / 128, 128, 0, s2>>>(x);
    k_fid<<<NFIDB, FTPB, 0, s2>>>(adj, x);
    cudaEventRecord(e1, s2);

    cudaStreamWaitEvent(0, e1, 0);   // join before k_post reads g_corr
    k_post<<<NN / 128, 128>>>(Wfm, bfm, Wc1, bc1, Wp1, bp1, Wc2, bc2,
                              Wp2, bp2, Wc3, bc3, Wh, bh, out);
}